// round 3
// baseline (speedup 1.0000x reference)
#include <cuda_runtime.h>
#include <cstdint>

#define NU    100000
#define NI    50000
#define NN    150000            // NU + NI
#define D     64
#define NNZ_  8000000
#define HOPS  3

// Ping-pong node-state buffers (38.4 MB each) — static __device__ per harness rules.
__device__ float g_bufA[(size_t)NN * D];   // current agg (SpMM source)
__device__ float g_bufB[(size_t)NN * D];   // accumulator  (SpMM dest)

// ---------------------------------------------------------------------------
// Init: bufA = concat(user, item); bufB = 0; out[:, hop0, :] = bufA
// ---------------------------------------------------------------------------
__global__ void init_kernel(const float* __restrict__ user,
                            const float* __restrict__ item,
                            float* __restrict__ out) {
    int idx = blockIdx.x * blockDim.x + threadIdx.x;
    const int total = NN * D / 4;           // 2,400,000
    if (idx >= total) return;
    const int userF4 = NU * D / 4;          // 1,600,000
    float4 v = (idx < userF4) ? ((const float4*)user)[idx]
                              : ((const float4*)item)[idx - userF4];
    ((float4*)g_bufA)[idx] = v;
    ((float4*)g_bufB)[idx] = make_float4(0.f, 0.f, 0.f, 0.f);
    int node = idx >> 4;                    // D/4 = 16 float4 per node
    int f4   = idx & 15;
    __stcs((float4*)out + (size_t)node * 64 + f4, v);   // hop 0 slice (streaming)
}

// ---------------------------------------------------------------------------
// Edge-dropout SpMM: bufB[row] += 2*val * bufA[col] for kept edges (erand>=0.5).
// Warp loads 32 edges (streaming, evict-first), ballots, then processes kept
// edges FOUR at a time: 8 lanes per edge, 2x float4 gather + 2x red.v4 each.
// Edge streams use __ldcs so the 2x38MB node buffers stay L2-resident.
// ---------------------------------------------------------------------------
__global__ void spmm_kernel(const int*   __restrict__ rows,
                            const int*   __restrict__ cols,
                            const float* __restrict__ vals,
                            const float* __restrict__ erand) {
    const int gtid   = blockIdx.x * blockDim.x + threadIdx.x;
    const int warp   = gtid >> 5;
    const int lane   = gtid & 31;
    const int nwarps = (gridDim.x * blockDim.x) >> 5;
    const int grp    = lane >> 3;    // which of the 4 concurrent edges (0..3)
    const int sub8   = lane & 7;     // 8 lanes per edge, 32B (2 float4) per lane

    const float* __restrict__ src = g_bufA;
    float*       __restrict__ dst = g_bufB;

    for (int base = warp * 32; base < NNZ_; base += nwarps * 32) {
        int e = base + lane;
        bool inb  = (e < NNZ_);
        float u   = inb ? __ldcs(erand + e) : 0.f;
        bool keep = inb && (u >= 0.5f);
        float v = 0.f; int r = 0, c = 0;
        if (keep) {                          // only touch metadata for kept edges
            v = __ldcs(vals + e) * 2.0f;     // 1/(1-0.5)
            r = __ldcs(rows + e);
            c = __ldcs(cols + e);
        }
        unsigned mask = __ballot_sync(0xFFFFFFFFu, keep);
        while (mask) {
            unsigned sl = __fns(mask, 0, grp + 1);   // (grp+1)-th set bit
            bool act  = (sl != 0xFFFFFFFFu);
            int  srcl = act ? (int)sl : 0;
            float vv = __shfl_sync(0xFFFFFFFFu, v, srcl);
            int   rr = __shfl_sync(0xFFFFFFFFu, r, srcl);
            int   cc = __shfl_sync(0xFFFFFFFFu, c, srcl);
            if (act) {
                const float4* sp = (const float4*)(src + (size_t)cc * D) + sub8 * 2;
                float4 x0 = __ldg(sp);
                float4 x1 = __ldg(sp + 1);
                x0.x *= vv; x0.y *= vv; x0.z *= vv; x0.w *= vv;
                x1.x *= vv; x1.y *= vv; x1.z *= vv; x1.w *= vv;
                float* a0 = dst + (size_t)rr * D + sub8 * 8;
                asm volatile("red.global.add.v4.f32 [%0], {%1, %2, %3, %4};"
                             :: "l"(a0), "f"(x0.x), "f"(x0.y), "f"(x0.z), "f"(x0.w)
                             : "memory");
                asm volatile("red.global.add.v4.f32 [%0], {%1, %2, %3, %4};"
                             :: "l"(a0 + 4), "f"(x1.x), "f"(x1.y), "f"(x1.z), "f"(x1.w)
                             : "memory");
            }
            // strip 4 lowest set bits (safe at 0: 0 & 0xFFFFFFFF == 0)
            mask &= mask - 1;
            mask &= mask - 1;
            mask &= mask - 1;
            mask &= mask - 1;
        }
    }
}

// ---------------------------------------------------------------------------
// Message dropout + epilogue: a = bufB * (mrand>=0.1) / 0.9
//   out[:, hop+1, :] = a ; bufA = a ; bufB = 0 (ready for next hop / replay)
// ---------------------------------------------------------------------------
__global__ void dropout_kernel(const float* __restrict__ mrand,
                               float* __restrict__ out,
                               int hop) {
    int idx = blockIdx.x * blockDim.x + threadIdx.x;
    const int total = NN * D / 4;
    if (idx >= total) return;
    float4 a = ((float4*)g_bufB)[idx];
    float4 m = __ldcs((const float4*)mrand + idx);   // streaming, read-once
    const float s = 1.0f / 0.9f;
    a.x = (m.x >= 0.1f) ? a.x * s : 0.f;
    a.y = (m.y >= 0.1f) ? a.y * s : 0.f;
    a.z = (m.z >= 0.1f) ? a.z * s : 0.f;
    a.w = (m.w >= 0.1f) ? a.w * s : 0.f;
    ((float4*)g_bufB)[idx] = make_float4(0.f, 0.f, 0.f, 0.f);
    ((float4*)g_bufA)[idx] = a;
    int node = idx >> 4;
    int f4   = idx & 15;
    __stcs((float4*)out + (size_t)node * 64 + (size_t)(hop + 1) * 16 + f4, a);
}

// ---------------------------------------------------------------------------
extern "C" void kernel_launch(void* const* d_in, const int* in_sizes, int n_in,
                              void* d_out, int out_size) {
    const float* user  = (const float*)d_in[0];
    const float* item  = (const float*)d_in[1];
    const int*   rows  = (const int*)  d_in[2];
    const int*   cols  = (const int*)  d_in[3];
    const float* vals  = (const float*)d_in[4];
    const float* erand = (const float*)d_in[5];
    const float* mrand = (const float*)d_in[6];
    float*       out   = (float*)d_out;

    const int totalF4   = NN * D / 4;
    const int ewThreads = 256;
    const int ewBlocks  = (totalF4 + ewThreads - 1) / ewThreads;   // 9375

    const int spThreads = 256;
    const int spBlocks  = 148 * 24;                                // grid-stride

    init_kernel<<<ewBlocks, ewThreads>>>(user, item, out);
    for (int hop = 0; hop < HOPS; ++hop) {
        spmm_kernel<<<spBlocks, spThreads>>>(rows, cols, vals,
                                             erand + (size_t)hop * NNZ_);
        dropout_kernel<<<ewBlocks, ewThreads>>>(mrand + (size_t)hop * NN * D,
                                                out, hop);
    }
}

// round 4
// speedup vs baseline: 1.0025x; 1.0025x over previous
#include <cuda_runtime.h>
#include <cstdint>

#define NU    100000
#define NI    50000
#define NN    150000            // NU + NI
#define D     64
#define NNZ_  8000000
#define HOPS  3

// Ping-pong node-state buffers (38.4 MB each) — static __device__ per harness rules.
__device__ float g_bufA[(size_t)NN * D];   // current agg (SpMM source)
__device__ float g_bufB[(size_t)NN * D];   // accumulator  (SpMM dest)

// ---------------------------------------------------------------------------
// Init: bufA = concat(user, item); bufB = 0; out[:, hop0, :] = bufA
// ---------------------------------------------------------------------------
__global__ void init_kernel(const float* __restrict__ user,
                            const float* __restrict__ item,
                            float* __restrict__ out) {
    int idx = blockIdx.x * blockDim.x + threadIdx.x;
    const int total = NN * D / 4;           // 2,400,000
    if (idx >= total) return;
    const int userF4 = NU * D / 4;          // 1,600,000
    float4 v = (idx < userF4) ? ((const float4*)user)[idx]
                              : ((const float4*)item)[idx - userF4];
    ((float4*)g_bufA)[idx] = v;
    ((float4*)g_bufB)[idx] = make_float4(0.f, 0.f, 0.f, 0.f);
    int node = idx >> 4;                    // D/4 = 16 float4 per node
    int f4   = idx & 15;
    __stcs((float4*)out + (size_t)node * 64 + f4, v);   // hop 0 slice (streaming)
}

// ---------------------------------------------------------------------------
// Edge-dropout SpMM: bufB[row] += 2*val * bufA[col] for kept edges (erand>=0.5).
// Warp loads 32 edges (streaming loads: edge arrays must not evict the
// L2-resident node buffers), ballots, then processes kept edges FOUR at a
// time: 8 lanes per edge, 2x float4 gathers (issued together, MLP=2) then
// 2x red.global.add.v4.f32. Bit extraction is a cheap serial __ffs chain.
// ---------------------------------------------------------------------------
__global__ void spmm_kernel(const int*   __restrict__ rows,
                            const int*   __restrict__ cols,
                            const float* __restrict__ vals,
                            const float* __restrict__ erand) {
    const int gtid   = blockIdx.x * blockDim.x + threadIdx.x;
    const int warp   = gtid >> 5;
    const int lane   = gtid & 31;
    const int nwarps = (gridDim.x * blockDim.x) >> 5;
    const int grp    = lane >> 3;    // which of the 4 concurrent edges (0..3)
    const int sub8   = lane & 7;     // 8 lanes per edge, 32B (2 float4) per lane

    const float* __restrict__ src = g_bufA;
    float*       __restrict__ dst = g_bufB;

    for (int base = warp * 32; base < NNZ_; base += nwarps * 32) {
        int e = base + lane;
        bool inb  = (e < NNZ_);
        float u   = inb ? __ldcs(erand + e) : 0.f;
        bool keep = inb && (u >= 0.5f);
        float v = 0.f; int r = 0, c = 0;
        if (keep) {                          // only touch metadata for kept edges
            v = __ldcs(vals + e) * 2.0f;     // 1/(1-0.5)
            r = __ldcs(rows + e);
            c = __ldcs(cols + e);
        }
        unsigned mask = __ballot_sync(0xFFFFFFFFu, keep);
        while (mask) {
            // Extract the 4 lowest set bits (32 = "none") with cheap ALU ops.
            int l0 = __ffs(mask) - 1;              mask &= mask - 1;
            int l1 = mask ? __ffs(mask) - 1 : 32;  mask &= mask - 1;
            int l2 = mask ? __ffs(mask) - 1 : 32;  mask &= mask - 1;
            int l3 = mask ? __ffs(mask) - 1 : 32;  mask &= mask - 1;
            int myl = (grp == 0) ? l0 : (grp == 1) ? l1 : (grp == 2) ? l2 : l3;
            bool act  = (myl < 32);
            int  srcl = act ? myl : 0;
            float vv = __shfl_sync(0xFFFFFFFFu, v, srcl);
            int   rr = __shfl_sync(0xFFFFFFFFu, r, srcl);
            int   cc = __shfl_sync(0xFFFFFFFFu, c, srcl);
            if (act) {
                const float4* sp = (const float4*)(src + (size_t)cc * D) + sub8 * 2;
                float4 x0 = __ldg(sp);
                float4 x1 = __ldg(sp + 1);
                x0.x *= vv; x0.y *= vv; x0.z *= vv; x0.w *= vv;
                x1.x *= vv; x1.y *= vv; x1.z *= vv; x1.w *= vv;
                float* a0 = dst + (size_t)rr * D + sub8 * 8;
                asm volatile("red.global.add.v4.f32 [%0], {%1, %2, %3, %4};"
                             :: "l"(a0), "f"(x0.x), "f"(x0.y), "f"(x0.z), "f"(x0.w)
                             : "memory");
                asm volatile("red.global.add.v4.f32 [%0], {%1, %2, %3, %4};"
                             :: "l"(a0 + 4), "f"(x1.x), "f"(x1.y), "f"(x1.z), "f"(x1.w)
                             : "memory");
            }
        }
    }
}

// ---------------------------------------------------------------------------
// Message dropout + epilogue: a = bufB * (mrand>=0.1) / 0.9
//   out[:, hop+1, :] = a ; bufA = a ; bufB = 0 (ready for next hop / replay)
// ---------------------------------------------------------------------------
__global__ void dropout_kernel(const float* __restrict__ mrand,
                               float* __restrict__ out,
                               int hop) {
    int idx = blockIdx.x * blockDim.x + threadIdx.x;
    const int total = NN * D / 4;
    if (idx >= total) return;
    float4 a = ((float4*)g_bufB)[idx];
    float4 m = __ldcs((const float4*)mrand + idx);   // streaming, read-once
    const float s = 1.0f / 0.9f;
    a.x = (m.x >= 0.1f) ? a.x * s : 0.f;
    a.y = (m.y >= 0.1f) ? a.y * s : 0.f;
    a.z = (m.z >= 0.1f) ? a.z * s : 0.f;
    a.w = (m.w >= 0.1f) ? a.w * s : 0.f;
    ((float4*)g_bufB)[idx] = make_float4(0.f, 0.f, 0.f, 0.f);
    ((float4*)g_bufA)[idx] = a;
    int node = idx >> 4;
    int f4   = idx & 15;
    __stcs((float4*)out + (size_t)node * 64 + (size_t)(hop + 1) * 16 + f4, a);
}

// ---------------------------------------------------------------------------
extern "C" void kernel_launch(void* const* d_in, const int* in_sizes, int n_in,
                              void* d_out, int out_size) {
    const float* user  = (const float*)d_in[0];
    const float* item  = (const float*)d_in[1];
    const int*   rows  = (const int*)  d_in[2];
    const int*   cols  = (const int*)  d_in[3];
    const float* vals  = (const float*)d_in[4];
    const float* erand = (const float*)d_in[5];
    const float* mrand = (const float*)d_in[6];
    float*       out   = (float*)d_out;

    const int totalF4   = NN * D / 4;
    const int ewThreads = 256;
    const int ewBlocks  = (totalF4 + ewThreads - 1) / ewThreads;   // 9375

    const int spThreads = 256;
    const int spBlocks  = 148 * 24;                                // grid-stride

    init_kernel<<<ewBlocks, ewThreads>>>(user, item, out);
    for (int hop = 0; hop < HOPS; ++hop) {
        spmm_kernel<<<spBlocks, spThreads>>>(rows, cols, vals,
                                             erand + (size_t)hop * NNZ_);
        dropout_kernel<<<ewBlocks, ewThreads>>>(mrand + (size_t)hop * NN * D,
                                                out, hop);
    }
}

// round 5
// speedup vs baseline: 1.3617x; 1.3583x over previous
#include <cuda_runtime.h>
#include <cstdint>

#define NU    100000
#define NI    50000
#define NN    150000            // NU + NI
#define D     64
#define NNZ_  8000000
#define HOPS  3

// Ping-pong node-state buffers (38.4 MB each) — static __device__ per harness rules.
__device__ float g_bufA[(size_t)NN * D];   // current agg (SpMM source)
__device__ float g_bufB[(size_t)NN * D];   // accumulator  (SpMM dest)

// ---------------------------------------------------------------------------
// Init: bufA = concat(user, item); bufB = 0; out[:, hop0, :] = bufA
// ---------------------------------------------------------------------------
__global__ void init_kernel(const float* __restrict__ user,
                            const float* __restrict__ item,
                            float* __restrict__ out) {
    int idx = blockIdx.x * blockDim.x + threadIdx.x;
    const int total = NN * D / 4;           // 2,400,000
    if (idx >= total) return;
    const int userF4 = NU * D / 4;          // 1,600,000
    float4 v = (idx < userF4) ? ((const float4*)user)[idx]
                              : ((const float4*)item)[idx - userF4];
    ((float4*)g_bufA)[idx] = v;
    ((float4*)g_bufB)[idx] = make_float4(0.f, 0.f, 0.f, 0.f);
    int node = idx >> 4;                    // D/4 = 16 float4 per node
    int f4   = idx & 15;
    __stcs((float4*)out + (size_t)node * 64 + f4, v);   // hop 0 slice (streaming)
}

// ---------------------------------------------------------------------------
// Edge-dropout SpMM: bufB[row] += 2*val * bufA[col] for kept edges (erand>=0.5).
// Warp loads 32 edges (streaming loads so edge arrays don't evict the
// L2-resident node buffers), ballots, then processes kept edges in DENSE
// 16-contiguous-lane groups (one float4 per lane = fully coalesced wavefronts
// for both the gather and the red.v4). Two edges per half-warp per iteration:
// both gathers issued before both reductions (MLP=2), all accesses dense.
// ---------------------------------------------------------------------------
__global__ void spmm_kernel(const int*   __restrict__ rows,
                            const int*   __restrict__ cols,
                            const float* __restrict__ vals,
                            const float* __restrict__ erand) {
    const int gtid   = blockIdx.x * blockDim.x + threadIdx.x;
    const int warp   = gtid >> 5;
    const int lane   = gtid & 31;
    const int nwarps = (gridDim.x * blockDim.x) >> 5;
    const int sub    = lane & 15;          // position within half-warp (float4 idx)
    const bool hi    = lane >= 16;         // half-warp id

    const float* __restrict__ src = g_bufA;
    float*       __restrict__ dst = g_bufB;

    for (int base = warp * 32; base < NNZ_; base += nwarps * 32) {
        int e = base + lane;
        bool inb  = (e < NNZ_);
        float u   = inb ? __ldcs(erand + e) : 0.f;
        bool keep = inb && (u >= 0.5f);
        float v = 0.f; int r = 0, c = 0;
        if (keep) {                          // only touch metadata for kept edges
            v = __ldcs(vals + e) * 2.0f;     // 1/(1-0.5)
            r = __ldcs(rows + e);
            c = __ldcs(cols + e);
        }
        unsigned mask = __ballot_sync(0xFFFFFFFFu, keep);
        while (mask) {
            // Extract up to 4 set bits (32 = "none").
            int l0 = __ffs(mask) - 1;              mask &= mask - 1;
            int l1 = mask ? __ffs(mask) - 1 : 32;  mask &= mask - 1;
            int l2 = mask ? __ffs(mask) - 1 : 32;  mask &= mask - 1;
            int l3 = mask ? __ffs(mask) - 1 : 32;  mask &= mask - 1;
            // half 0 processes edges l0,l2 ; half 1 processes l1,l3
            int eA = hi ? l1 : l0;
            int eB = hi ? l3 : l2;
            bool actA = eA < 32, actB = eB < 32;
            int sA = actA ? eA : 0, sB = actB ? eB : 0;
            float vA = __shfl_sync(0xFFFFFFFFu, v, sA);
            int   rA = __shfl_sync(0xFFFFFFFFu, r, sA);
            int   cA = __shfl_sync(0xFFFFFFFFu, c, sA);
            float vB = __shfl_sync(0xFFFFFFFFu, v, sB);
            int   rB = __shfl_sync(0xFFFFFFFFu, r, sB);
            int   cB = __shfl_sync(0xFFFFFFFFu, c, sB);
            float4 xA, xB;
            if (actA) xA = __ldg((const float4*)(src + (size_t)cA * D) + sub);
            if (actB) xB = __ldg((const float4*)(src + (size_t)cB * D) + sub);
            if (actA) {
                xA.x *= vA; xA.y *= vA; xA.z *= vA; xA.w *= vA;
                float* a = dst + (size_t)rA * D + sub * 4;
                asm volatile("red.global.add.v4.f32 [%0], {%1, %2, %3, %4};"
                             :: "l"(a), "f"(xA.x), "f"(xA.y), "f"(xA.z), "f"(xA.w)
                             : "memory");
            }
            if (actB) {
                xB.x *= vB; xB.y *= vB; xB.z *= vB; xB.w *= vB;
                float* a = dst + (size_t)rB * D + sub * 4;
                asm volatile("red.global.add.v4.f32 [%0], {%1, %2, %3, %4};"
                             :: "l"(a), "f"(xB.x), "f"(xB.y), "f"(xB.z), "f"(xB.w)
                             : "memory");
            }
        }
    }
}

// ---------------------------------------------------------------------------
// Message dropout + epilogue: a = bufB * (mrand>=0.1) / 0.9
//   out[:, hop+1, :] = a ; bufA = a ; bufB = 0 (ready for next hop / replay)
// ---------------------------------------------------------------------------
__global__ void dropout_kernel(const float* __restrict__ mrand,
                               float* __restrict__ out,
                               int hop) {
    int idx = blockIdx.x * blockDim.x + threadIdx.x;
    const int total = NN * D / 4;
    if (idx >= total) return;
    float4 a = ((float4*)g_bufB)[idx];
    float4 m = __ldcs((const float4*)mrand + idx);   // streaming, read-once
    const float s = 1.0f / 0.9f;
    a.x = (m.x >= 0.1f) ? a.x * s : 0.f;
    a.y = (m.y >= 0.1f) ? a.y * s : 0.f;
    a.z = (m.z >= 0.1f) ? a.z * s : 0.f;
    a.w = (m.w >= 0.1f) ? a.w * s : 0.f;
    ((float4*)g_bufB)[idx] = make_float4(0.f, 0.f, 0.f, 0.f);
    ((float4*)g_bufA)[idx] = a;
    int node = idx >> 4;
    int f4   = idx & 15;
    __stcs((float4*)out + (size_t)node * 64 + (size_t)(hop + 1) * 16 + f4, a);
}

// ---------------------------------------------------------------------------
extern "C" void kernel_launch(void* const* d_in, const int* in_sizes, int n_in,
                              void* d_out, int out_size) {
    const float* user  = (const float*)d_in[0];
    const float* item  = (const float*)d_in[1];
    const int*   rows  = (const int*)  d_in[2];
    const int*   cols  = (const int*)  d_in[3];
    const float* vals  = (const float*)d_in[4];
    const float* erand = (const float*)d_in[5];
    const float* mrand = (const float*)d_in[6];
    float*       out   = (float*)d_out;

    const int totalF4   = NN * D / 4;
    const int ewThreads = 256;
    const int ewBlocks  = (totalF4 + ewThreads - 1) / ewThreads;   // 9375

    const int spThreads = 256;
    const int spBlocks  = 148 * 24;                                // grid-stride

    init_kernel<<<ewBlocks, ewThreads>>>(user, item, out);
    for (int hop = 0; hop < HOPS; ++hop) {
        spmm_kernel<<<spBlocks, spThreads>>>(rows, cols, vals,
                                             erand + (size_t)hop * NNZ_);
        dropout_kernel<<<ewBlocks, ewThreads>>>(mrand + (size_t)hop * NN * D,
                                                out, hop);
    }
}

// round 6
// speedup vs baseline: 1.4224x; 1.0446x over previous
#include <cuda_runtime.h>
#include <cstdint>

#define NU    100000
#define NI    50000
#define NN    150000            // NU + NI
#define D     64
#define NNZ_  8000000
#define HOPS  3

// Ping-pong node-state buffers (38.4 MB each) — static __device__ per harness rules.
__device__ float g_bufA[(size_t)NN * D];   // current agg (SpMM source)
__device__ float g_bufB[(size_t)NN * D];   // accumulator  (SpMM dest)

// L2 policy: keep node buffers resident (evict_last).
__device__ __forceinline__ uint64_t evict_last_policy() {
    uint64_t pol;
    asm("createpolicy.fractional.L2::evict_last.b64 %0, 1.0;" : "=l"(pol));
    return pol;
}

__device__ __forceinline__ float4 ldg_evict_last_v4(const float4* p, uint64_t pol) {
    float4 x;
    asm("ld.global.nc.L2::cache_hint.v4.f32 {%0,%1,%2,%3}, [%4], %5;"
        : "=f"(x.x), "=f"(x.y), "=f"(x.z), "=f"(x.w)
        : "l"(p), "l"(pol));
    return x;
}

__device__ __forceinline__ void red_evict_last_v4(float* a, float4 x, uint64_t pol) {
    asm volatile("red.global.add.L2::cache_hint.v4.f32 [%0], {%1,%2,%3,%4}, %5;"
                 :: "l"(a), "f"(x.x), "f"(x.y), "f"(x.z), "f"(x.w), "l"(pol)
                 : "memory");
}

__device__ __forceinline__ void st_evict_last_v4(float4* p, float4 x, uint64_t pol) {
    asm volatile("st.global.L2::cache_hint.v4.f32 [%0], {%1,%2,%3,%4}, %5;"
                 :: "l"(p), "f"(x.x), "f"(x.y), "f"(x.z), "f"(x.w), "l"(pol)
                 : "memory");
}

__device__ __forceinline__ float4 ld_evict_last_v4(const float4* p, uint64_t pol) {
    float4 x;
    asm volatile("ld.global.L2::cache_hint.v4.f32 {%0,%1,%2,%3}, [%4], %5;"
                 : "=f"(x.x), "=f"(x.y), "=f"(x.z), "=f"(x.w)
                 : "l"(p), "l"(pol));
    return x;
}

// ---------------------------------------------------------------------------
// Init: bufA = concat(user, item); bufB = 0; out[:, hop0, :] = bufA
// ---------------------------------------------------------------------------
__global__ void init_kernel(const float* __restrict__ user,
                            const float* __restrict__ item,
                            float* __restrict__ out) {
    int idx = blockIdx.x * blockDim.x + threadIdx.x;
    const int total = NN * D / 4;           // 2,400,000
    if (idx >= total) return;
    const uint64_t pol = evict_last_policy();
    const int userF4 = NU * D / 4;          // 1,600,000
    float4 v = (idx < userF4) ? ((const float4*)user)[idx]
                              : ((const float4*)item)[idx - userF4];
    st_evict_last_v4((float4*)g_bufA + idx, v, pol);
    st_evict_last_v4((float4*)g_bufB + idx, make_float4(0.f, 0.f, 0.f, 0.f), pol);
    int node = idx >> 4;                    // D/4 = 16 float4 per node
    int f4   = idx & 15;
    __stcs((float4*)out + (size_t)node * 64 + f4, v);   // hop 0 slice (streaming)
}

// ---------------------------------------------------------------------------
// Edge-dropout SpMM: bufB[row] += 2*val * bufA[col] for kept edges (erand>=0.5).
// Edge streams: __ldcs (evict-first). Node buffers: evict_last policy so the
// 2x38MB working set stays L2-resident. Dense 16-lane x float4 layout, two
// edges per half-warp per iteration (gathers issued before reds, MLP=2).
// ---------------------------------------------------------------------------
__global__ void spmm_kernel(const int*   __restrict__ rows,
                            const int*   __restrict__ cols,
                            const float* __restrict__ vals,
                            const float* __restrict__ erand) {
    const int gtid   = blockIdx.x * blockDim.x + threadIdx.x;
    const int warp   = gtid >> 5;
    const int lane   = gtid & 31;
    const int nwarps = (gridDim.x * blockDim.x) >> 5;
    const int sub    = lane & 15;          // position within half-warp (float4 idx)
    const bool hi    = lane >= 16;         // half-warp id

    const uint64_t pol = evict_last_policy();
    const float* __restrict__ src = g_bufA;
    float*       __restrict__ dst = g_bufB;

    for (int base = warp * 32; base < NNZ_; base += nwarps * 32) {
        int e = base + lane;
        bool inb  = (e < NNZ_);
        float u   = inb ? __ldcs(erand + e) : 0.f;
        bool keep = inb && (u >= 0.5f);
        float v = 0.f; int r = 0, c = 0;
        if (keep) {                          // only touch metadata for kept edges
            v = __ldcs(vals + e) * 2.0f;     // 1/(1-0.5)
            r = __ldcs(rows + e);
            c = __ldcs(cols + e);
        }
        unsigned mask = __ballot_sync(0xFFFFFFFFu, keep);
        while (mask) {
            // Extract up to 4 set bits (32 = "none").
            int l0 = __ffs(mask) - 1;              mask &= mask - 1;
            int l1 = mask ? __ffs(mask) - 1 : 32;  mask &= mask - 1;
            int l2 = mask ? __ffs(mask) - 1 : 32;  mask &= mask - 1;
            int l3 = mask ? __ffs(mask) - 1 : 32;  mask &= mask - 1;
            // half 0 processes edges l0,l2 ; half 1 processes l1,l3
            int eA = hi ? l1 : l0;
            int eB = hi ? l3 : l2;
            bool actA = eA < 32, actB = eB < 32;
            int sA = actA ? eA : 0, sB = actB ? eB : 0;
            float vA = __shfl_sync(0xFFFFFFFFu, v, sA);
            int   rA = __shfl_sync(0xFFFFFFFFu, r, sA);
            int   cA = __shfl_sync(0xFFFFFFFFu, c, sA);
            float vB = __shfl_sync(0xFFFFFFFFu, v, sB);
            int   rB = __shfl_sync(0xFFFFFFFFu, r, sB);
            int   cB = __shfl_sync(0xFFFFFFFFu, c, sB);
            float4 xA, xB;
            if (actA) xA = ldg_evict_last_v4((const float4*)(src + (size_t)cA * D) + sub, pol);
            if (actB) xB = ldg_evict_last_v4((const float4*)(src + (size_t)cB * D) + sub, pol);
            if (actA) {
                xA.x *= vA; xA.y *= vA; xA.z *= vA; xA.w *= vA;
                red_evict_last_v4(dst + (size_t)rA * D + sub * 4, xA, pol);
            }
            if (actB) {
                xB.x *= vB; xB.y *= vB; xB.z *= vB; xB.w *= vB;
                red_evict_last_v4(dst + (size_t)rB * D + sub * 4, xB, pol);
            }
        }
    }
}

// ---------------------------------------------------------------------------
// Message dropout + epilogue: a = bufB * (mrand>=0.1) / 0.9
//   out[:, hop+1, :] = a ; bufA = a ; bufB = 0 (ready for next hop / replay)
// ---------------------------------------------------------------------------
__global__ void dropout_kernel(const float* __restrict__ mrand,
                               float* __restrict__ out,
                               int hop) {
    int idx = blockIdx.x * blockDim.x + threadIdx.x;
    const int total = NN * D / 4;
    if (idx >= total) return;
    const uint64_t pol = evict_last_policy();
    float4 a = ld_evict_last_v4((const float4*)g_bufB + idx, pol);
    float4 m = __ldcs((const float4*)mrand + idx);   // streaming, read-once
    const float s = 1.0f / 0.9f;
    a.x = (m.x >= 0.1f) ? a.x * s : 0.f;
    a.y = (m.y >= 0.1f) ? a.y * s : 0.f;
    a.z = (m.z >= 0.1f) ? a.z * s : 0.f;
    a.w = (m.w >= 0.1f) ? a.w * s : 0.f;
    st_evict_last_v4((float4*)g_bufB + idx, make_float4(0.f, 0.f, 0.f, 0.f), pol);
    st_evict_last_v4((float4*)g_bufA + idx, a, pol);
    int node = idx >> 4;
    int f4   = idx & 15;
    __stcs((float4*)out + (size_t)node * 64 + (size_t)(hop + 1) * 16 + f4, a);
}

// ---------------------------------------------------------------------------
extern "C" void kernel_launch(void* const* d_in, const int* in_sizes, int n_in,
                              void* d_out, int out_size) {
    const float* user  = (const float*)d_in[0];
    const float* item  = (const float*)d_in[1];
    const int*   rows  = (const int*)  d_in[2];
    const int*   cols  = (const int*)  d_in[3];
    const float* vals  = (const float*)d_in[4];
    const float* erand = (const float*)d_in[5];
    const float* mrand = (const float*)d_in[6];
    float*       out   = (float*)d_out;

    const int totalF4   = NN * D / 4;
    const int ewThreads = 512;
    const int ewBlocks  = (totalF4 + ewThreads - 1) / ewThreads;

    const int spThreads = 256;
    const int spBlocks  = 148 * 32;                                // grid-stride

    init_kernel<<<ewBlocks, ewThreads>>>(user, item, out);
    for (int hop = 0; hop < HOPS; ++hop) {
        spmm_kernel<<<spBlocks, spThreads>>>(rows, cols, vals,
                                             erand + (size_t)hop * NNZ_);
        dropout_kernel<<<ewBlocks, ewThreads>>>(mrand + (size_t)hop * NN * D,
                                                out, hop);
    }
}

// round 7
// speedup vs baseline: 1.5198x; 1.0684x over previous
#include <cuda_runtime.h>
#include <cstdint>

#define NU    100000
#define NI    50000
#define NN    150000            // NU + NI
#define D     64
#define NNZ_  8000000
#define HOPS  3

// SpMM accumulator (38.4 MB) — static __device__ per harness rules.
// The gather SOURCE is now the out[:, hop, :] slice itself (no bufA copy).
__device__ float g_bufB[(size_t)NN * D];

// L2 policy: keep hot buffers resident (evict_last).
__device__ __forceinline__ uint64_t evict_last_policy() {
    uint64_t pol;
    asm("createpolicy.fractional.L2::evict_last.b64 %0, 1.0;" : "=l"(pol));
    return pol;
}

__device__ __forceinline__ float4 ldg_evict_last_v4(const float4* p, uint64_t pol) {
    float4 x;
    asm("ld.global.nc.L2::cache_hint.v4.f32 {%0,%1,%2,%3}, [%4], %5;"
        : "=f"(x.x), "=f"(x.y), "=f"(x.z), "=f"(x.w)
        : "l"(p), "l"(pol));
    return x;
}

__device__ __forceinline__ void red_evict_last_v4(float* a, float4 x, uint64_t pol) {
    asm volatile("red.global.add.L2::cache_hint.v4.f32 [%0], {%1,%2,%3,%4}, %5;"
                 :: "l"(a), "f"(x.x), "f"(x.y), "f"(x.z), "f"(x.w), "l"(pol)
                 : "memory");
}

__device__ __forceinline__ void st_evict_last_v4(float4* p, float4 x, uint64_t pol) {
    asm volatile("st.global.L2::cache_hint.v4.f32 [%0], {%1,%2,%3,%4}, %5;"
                 :: "l"(p), "f"(x.x), "f"(x.y), "f"(x.z), "f"(x.w), "l"(pol)
                 : "memory");
}

__device__ __forceinline__ float4 ld_evict_last_v4(const float4* p, uint64_t pol) {
    float4 x;
    asm volatile("ld.global.L2::cache_hint.v4.f32 {%0,%1,%2,%3}, [%4], %5;"
                 : "=f"(x.x), "=f"(x.y), "=f"(x.z), "=f"(x.w)
                 : "l"(p), "l"(pol));
    return x;
}

// ---------------------------------------------------------------------------
// Tiny prologue kernel: shifts launch indices so ncu (-s 5 -c 1) profiles a
// dropout kernel instead of the 3rd spmm. Deterministic (bufB[0] is re-zeroed
// by init_kernel right after anyway).
// ---------------------------------------------------------------------------
__global__ void prof_shift_kernel() {
    if (blockIdx.x == 0 && threadIdx.x == 0) g_bufB[0] = 0.f;
}

// ---------------------------------------------------------------------------
// Init: out[:, 0, :] = concat(user, item); bufB = 0
// ---------------------------------------------------------------------------
__global__ void init_kernel(const float* __restrict__ user,
                            const float* __restrict__ item,
                            float* __restrict__ out) {
    int idx = blockIdx.x * blockDim.x + threadIdx.x;
    const int total = NN * D / 4;           // 2,400,000
    if (idx >= total) return;
    const uint64_t pol = evict_last_policy();
    const int userF4 = NU * D / 4;          // 1,600,000
    float4 v = (idx < userF4) ? ((const float4*)user)[idx]
                              : ((const float4*)item)[idx - userF4];
    ((float4*)g_bufB)[idx] = make_float4(0.f, 0.f, 0.f, 0.f);
    int node = idx >> 4;                    // D/4 = 16 float4 per node
    int f4   = idx & 15;
    // hop-0 slice: gather source for spmm hop 0 → keep L2-resident
    st_evict_last_v4((float4*)out + (size_t)node * 64 + f4, v, pol);
}

// ---------------------------------------------------------------------------
// Edge-dropout SpMM: bufB[row] += 2*val * src[col] for kept edges (erand>=0.5)
// where src = out[:, hop, :] (node stride 256 floats, row = dense 256B).
// Edge streams: __ldcs (evict-first). Dense 16-lane x float4 layout, two
// edges per half-warp per iteration (gathers issued before reds, MLP=2).
// ---------------------------------------------------------------------------
__global__ void spmm_kernel(const int*   __restrict__ rows,
                            const int*   __restrict__ cols,
                            const float* __restrict__ vals,
                            const float* __restrict__ erand,
                            const float* __restrict__ src) {   // = out + hop*64
    const int gtid   = blockIdx.x * blockDim.x + threadIdx.x;
    const int warp   = gtid >> 5;
    const int lane   = gtid & 31;
    const int nwarps = (gridDim.x * blockDim.x) >> 5;
    const int sub    = lane & 15;          // position within half-warp (float4 idx)
    const bool hi    = lane >= 16;         // half-warp id

    const uint64_t pol = evict_last_policy();
    float* __restrict__ dst = g_bufB;

    for (int base = warp * 32; base < NNZ_; base += nwarps * 32) {
        int e = base + lane;
        bool inb  = (e < NNZ_);
        float u   = inb ? __ldcs(erand + e) : 0.f;
        bool keep = inb && (u >= 0.5f);
        float v = 0.f; int r = 0, c = 0;
        if (keep) {                          // only touch metadata for kept edges
            v = __ldcs(vals + e) * 2.0f;     // 1/(1-0.5)
            r = __ldcs(rows + e);
            c = __ldcs(cols + e);
        }
        unsigned mask = __ballot_sync(0xFFFFFFFFu, keep);
        while (mask) {
            // Extract up to 4 set bits (32 = "none").
            int l0 = __ffs(mask) - 1;              mask &= mask - 1;
            int l1 = mask ? __ffs(mask) - 1 : 32;  mask &= mask - 1;
            int l2 = mask ? __ffs(mask) - 1 : 32;  mask &= mask - 1;
            int l3 = mask ? __ffs(mask) - 1 : 32;  mask &= mask - 1;
            // half 0 processes edges l0,l2 ; half 1 processes l1,l3
            int eA = hi ? l1 : l0;
            int eB = hi ? l3 : l2;
            bool actA = eA < 32, actB = eB < 32;
            int sA = actA ? eA : 0, sB = actB ? eB : 0;
            float vA = __shfl_sync(0xFFFFFFFFu, v, sA);
            int   rA = __shfl_sync(0xFFFFFFFFu, r, sA);
            int   cA = __shfl_sync(0xFFFFFFFFu, c, sA);
            float vB = __shfl_sync(0xFFFFFFFFu, v, sB);
            int   rB = __shfl_sync(0xFFFFFFFFu, r, sB);
            int   cB = __shfl_sync(0xFFFFFFFFu, c, sB);
            float4 xA, xB;
            if (actA) xA = ldg_evict_last_v4((const float4*)(src + (size_t)cA * 256) + sub, pol);
            if (actB) xB = ldg_evict_last_v4((const float4*)(src + (size_t)cB * 256) + sub, pol);
            if (actA) {
                xA.x *= vA; xA.y *= vA; xA.z *= vA; xA.w *= vA;
                red_evict_last_v4(dst + (size_t)rA * D + sub * 4, xA, pol);
            }
            if (actB) {
                xB.x *= vB; xB.y *= vB; xB.z *= vB; xB.w *= vB;
                red_evict_last_v4(dst + (size_t)rB * D + sub * 4, xB, pol);
            }
        }
    }
}

// ---------------------------------------------------------------------------
// Message dropout + epilogue: a = bufB * (mrand>=0.1) / 0.9
//   out[:, hop+1, :] = a (next hop's gather source) ; bufB = 0
// ---------------------------------------------------------------------------
__global__ void dropout_kernel(const float* __restrict__ mrand,
                               float* __restrict__ out,
                               int hop) {
    int idx = blockIdx.x * blockDim.x + threadIdx.x;
    const int total = NN * D / 4;
    if (idx >= total) return;
    const uint64_t pol = evict_last_policy();
    float4 a = ld_evict_last_v4((const float4*)g_bufB + idx, pol);
    float4 m = __ldcs((const float4*)mrand + idx);   // streaming, read-once
    const float s = 1.0f / 0.9f;
    a.x = (m.x >= 0.1f) ? a.x * s : 0.f;
    a.y = (m.y >= 0.1f) ? a.y * s : 0.f;
    a.z = (m.z >= 0.1f) ? a.z * s : 0.f;
    a.w = (m.w >= 0.1f) ? a.w * s : 0.f;
    ((float4*)g_bufB)[idx] = make_float4(0.f, 0.f, 0.f, 0.f);
    int node = idx >> 4;
    int f4   = idx & 15;
    st_evict_last_v4((float4*)out + (size_t)node * 64 + (size_t)(hop + 1) * 16 + f4,
                     a, pol);
}

// ---------------------------------------------------------------------------
extern "C" void kernel_launch(void* const* d_in, const int* in_sizes, int n_in,
                              void* d_out, int out_size) {
    const float* user  = (const float*)d_in[0];
    const float* item  = (const float*)d_in[1];
    const int*   rows  = (const int*)  d_in[2];
    const int*   cols  = (const int*)  d_in[3];
    const float* vals  = (const float*)d_in[4];
    const float* erand = (const float*)d_in[5];
    const float* mrand = (const float*)d_in[6];
    float*       out   = (float*)d_out;

    const int totalF4   = NN * D / 4;
    const int ewThreads = 512;
    const int ewBlocks  = (totalF4 + ewThreads - 1) / ewThreads;

    const int spThreads = 256;
    const int spBlocks  = 148 * 32;                                // grid-stride

    // Launch order (ncu uses -s 5 -c 1 → profiles index 5 = dropout hop 1):
    // 0 prof_shift, 1 init, 2 spmm0, 3 drop0, 4 spmm1, 5 drop1, 6 spmm2, 7 drop2
    prof_shift_kernel<<<1, 32>>>();
    init_kernel<<<ewBlocks, ewThreads>>>(user, item, out);
    for (int hop = 0; hop < HOPS; ++hop) {
        spmm_kernel<<<spBlocks, spThreads>>>(rows, cols, vals,
                                             erand + (size_t)hop * NNZ_,
                                             out + (size_t)hop * 64);
        dropout_kernel<<<ewBlocks, ewThreads>>>(mrand + (size_t)hop * NN * D,
                                                out, hop);
    }
}

// round 8
// speedup vs baseline: 1.7404x; 1.1452x over previous
#include <cuda_runtime.h>
#include <cstdint>

#define NU    100000
#define NI    50000
#define NN    150000            // NU + NI
#define D     64
#define NNZ_  8000000
#define HOPS  3

// SpMM accumulator (38.4 MB) — static __device__ per harness rules.
// The gather SOURCE is the out[:, hop, :] slice itself (no separate copy).
__device__ float g_bufB[(size_t)NN * D];

// L2 policy: keep hot buffers resident (evict_last).
__device__ __forceinline__ uint64_t evict_last_policy() {
    uint64_t pol;
    asm("createpolicy.fractional.L2::evict_last.b64 %0, 1.0;" : "=l"(pol));
    return pol;
}

__device__ __forceinline__ float4 ldg_evict_last_v4(const float4* p, uint64_t pol) {
    float4 x;
    asm("ld.global.nc.L2::cache_hint.v4.f32 {%0,%1,%2,%3}, [%4], %5;"
        : "=f"(x.x), "=f"(x.y), "=f"(x.z), "=f"(x.w)
        : "l"(p), "l"(pol));
    return x;
}

__device__ __forceinline__ void red_evict_last_v4(float* a, float4 x, uint64_t pol) {
    asm volatile("red.global.add.L2::cache_hint.v4.f32 [%0], {%1,%2,%3,%4}, %5;"
                 :: "l"(a), "f"(x.x), "f"(x.y), "f"(x.z), "f"(x.w), "l"(pol)
                 : "memory");
}

__device__ __forceinline__ void st_evict_last_v4(float4* p, float4 x, uint64_t pol) {
    asm volatile("st.global.L2::cache_hint.v4.f32 [%0], {%1,%2,%3,%4}, %5;"
                 :: "l"(p), "f"(x.x), "f"(x.y), "f"(x.z), "f"(x.w), "l"(pol)
                 : "memory");
}

// ---------------------------------------------------------------------------
// Init: out[:, 0, :] = concat(user, item); bufB = 0
// 4 float4 (64B) per thread: batched independent loads for latency hiding.
// ---------------------------------------------------------------------------
__global__ void init_kernel(const float* __restrict__ user,
                            const float* __restrict__ item,
                            float* __restrict__ out) {
    int t = blockIdx.x * blockDim.x + threadIdx.x;
    const int total = NN * D / 16;          // 600,000 threads
    if (t >= total) return;
    const uint64_t pol = evict_last_policy();
    const int base   = t * 4;               // float4 index, aligned to 4
    const int userF4 = NU * D / 4;
    float4 v[4];
    #pragma unroll
    for (int i = 0; i < 4; ++i) {
        int idx = base + i;
        v[i] = (idx < userF4) ? ((const float4*)user)[idx]
                              : ((const float4*)item)[idx - userF4];
    }
    #pragma unroll
    for (int i = 0; i < 4; ++i)
        ((float4*)g_bufB)[base + i] = make_float4(0.f, 0.f, 0.f, 0.f);
    const int node = base >> 4;             // 16 float4 per node; base%16 in {0,4,8,12}
    const int f4   = base & 15;
    #pragma unroll
    for (int i = 0; i < 4; ++i)             // hop-0 slice: next spmm's gather source
        st_evict_last_v4((float4*)out + (size_t)node * 64 + f4 + i, v[i], pol);
}

// ---------------------------------------------------------------------------
// Edge-dropout SpMM: bufB[row] += 2*val * src[col] for kept edges (erand>=0.5)
// where src = out[:, hop, :] (node stride 256 floats, row = dense 256B).
// Edge streams: __ldcs (evict-first). Dense 16-lane x float4 layout, two
// edges per half-warp per iteration (gathers issued before reds, MLP=2).
// ---------------------------------------------------------------------------
__global__ void spmm_kernel(const int*   __restrict__ rows,
                            const int*   __restrict__ cols,
                            const float* __restrict__ vals,
                            const float* __restrict__ erand,
                            const float* __restrict__ src) {   // = out + hop*64
    const int gtid   = blockIdx.x * blockDim.x + threadIdx.x;
    const int warp   = gtid >> 5;
    const int lane   = gtid & 31;
    const int nwarps = (gridDim.x * blockDim.x) >> 5;
    const int sub    = lane & 15;          // position within half-warp (float4 idx)
    const bool hi    = lane >= 16;         // half-warp id

    const uint64_t pol = evict_last_policy();
    float* __restrict__ dst = g_bufB;

    for (int base = warp * 32; base < NNZ_; base += nwarps * 32) {
        int e = base + lane;
        bool inb  = (e < NNZ_);
        float u   = inb ? __ldcs(erand + e) : 0.f;
        bool keep = inb && (u >= 0.5f);
        float v = 0.f; int r = 0, c = 0;
        if (keep) {                          // only touch metadata for kept edges
            v = __ldcs(vals + e) * 2.0f;     // 1/(1-0.5)
            r = __ldcs(rows + e);
            c = __ldcs(cols + e);
        }
        unsigned mask = __ballot_sync(0xFFFFFFFFu, keep);
        while (mask) {
            // Extract up to 4 set bits (32 = "none").
            int l0 = __ffs(mask) - 1;              mask &= mask - 1;
            int l1 = mask ? __ffs(mask) - 1 : 32;  mask &= mask - 1;
            int l2 = mask ? __ffs(mask) - 1 : 32;  mask &= mask - 1;
            int l3 = mask ? __ffs(mask) - 1 : 32;  mask &= mask - 1;
            // half 0 processes edges l0,l2 ; half 1 processes l1,l3
            int eA = hi ? l1 : l0;
            int eB = hi ? l3 : l2;
            bool actA = eA < 32, actB = eB < 32;
            int sA = actA ? eA : 0, sB = actB ? eB : 0;
            float vA = __shfl_sync(0xFFFFFFFFu, v, sA);
            int   rA = __shfl_sync(0xFFFFFFFFu, r, sA);
            int   cA = __shfl_sync(0xFFFFFFFFu, c, sA);
            float vB = __shfl_sync(0xFFFFFFFFu, v, sB);
            int   rB = __shfl_sync(0xFFFFFFFFu, r, sB);
            int   cB = __shfl_sync(0xFFFFFFFFu, c, sB);
            float4 xA, xB;
            if (actA) xA = ldg_evict_last_v4((const float4*)(src + (size_t)cA * 256) + sub, pol);
            if (actB) xB = ldg_evict_last_v4((const float4*)(src + (size_t)cB * 256) + sub, pol);
            if (actA) {
                xA.x *= vA; xA.y *= vA; xA.z *= vA; xA.w *= vA;
                red_evict_last_v4(dst + (size_t)rA * D + sub * 4, xA, pol);
            }
            if (actB) {
                xB.x *= vB; xB.y *= vB; xB.z *= vB; xB.w *= vB;
                red_evict_last_v4(dst + (size_t)rB * D + sub * 4, xB, pol);
            }
        }
    }
}

// ---------------------------------------------------------------------------
// Message dropout + epilogue: a = bufB * (mrand>=0.1) / 0.9
//   out[:, hop+1, :] = a (next hop's gather source) ; bufB = 0
// 4 float4 (64B) per thread: 8 independent loads in flight before compute.
// ---------------------------------------------------------------------------
__global__ void dropout_kernel(const float* __restrict__ mrand,
                               float* __restrict__ out,
                               int hop) {
    int t = blockIdx.x * blockDim.x + threadIdx.x;
    const int total = NN * D / 16;          // 600,000 threads
    if (t >= total) return;
    const uint64_t pol = evict_last_policy();
    const int base = t * 4;
    float4 a[4], m[4];
    #pragma unroll
    for (int i = 0; i < 4; ++i) a[i] = ((const float4*)g_bufB)[base + i];
    #pragma unroll
    for (int i = 0; i < 4; ++i) m[i] = __ldcs((const float4*)mrand + base + i);
    const float s = 1.0f / 0.9f;
    #pragma unroll
    for (int i = 0; i < 4; ++i) {
        a[i].x = (m[i].x >= 0.1f) ? a[i].x * s : 0.f;
        a[i].y = (m[i].y >= 0.1f) ? a[i].y * s : 0.f;
        a[i].z = (m[i].z >= 0.1f) ? a[i].z * s : 0.f;
        a[i].w = (m[i].w >= 0.1f) ? a[i].w * s : 0.f;
    }
    #pragma unroll
    for (int i = 0; i < 4; ++i)
        ((float4*)g_bufB)[base + i] = make_float4(0.f, 0.f, 0.f, 0.f);
    const int node = base >> 4;
    const int f4   = base & 15;
    float4* op = (float4*)out + (size_t)node * 64 + (size_t)(hop + 1) * 16 + f4;
    #pragma unroll
    for (int i = 0; i < 4; ++i)
        st_evict_last_v4(op + i, a[i], pol);
}

// ---------------------------------------------------------------------------
extern "C" void kernel_launch(void* const* d_in, const int* in_sizes, int n_in,
                              void* d_out, int out_size) {
    const float* user  = (const float*)d_in[0];
    const float* item  = (const float*)d_in[1];
    const int*   rows  = (const int*)  d_in[2];
    const int*   cols  = (const int*)  d_in[3];
    const float* vals  = (const float*)d_in[4];
    const float* erand = (const float*)d_in[5];
    const float* mrand = (const float*)d_in[6];
    float*       out   = (float*)d_out;

    const int totalT    = NN * D / 16;      // 600,000
    const int ewThreads = 256;
    const int ewBlocks  = (totalT + ewThreads - 1) / ewThreads;   // 2344

    const int spThreads = 256;
    const int spBlocks  = 148 * 32;                               // grid-stride

    // Launch order: 0 init, 1 spmm0, 2 drop0, 3 spmm1, 4 drop1, 5 spmm2 ...
    // ncu -s 5 -c 1 → profiles spmm hop 2.
    init_kernel<<<ewBlocks, ewThreads>>>(user, item, out);
    for (int hop = 0; hop < HOPS; ++hop) {
        spmm_kernel<<<spBlocks, spThreads>>>(rows, cols, vals,
                                             erand + (size_t)hop * NNZ_,
                                             out + (size_t)hop * 64);
        dropout_kernel<<<ewBlocks, ewThreads>>>(mrand + (size_t)hop * NN * D,
                                                out, hop);
    }
}